// round 13
// baseline (speedup 1.0000x reference)
#include <cuda_runtime.h>
#include <cuda_bf16.h>
#include <cstdint>
#include <math.h>

// ============================================================================
// InfoNCE / NT-Xent via mma.sync bf16 m16n8k16 + ldmatrix, sim = sim^T
// (upper-triangular 128x128 tiles, 2080). Persistent 296 CTAs (2/SM).
// Main kernel byte-identical to the 62.0us R11 winner. Changes:
//   - slim prep: init ONLY the 16 row-strip slots (col slots 16+I are fully
//     written by tile (I,J) for every row of block J before being read)
//   - adaptive reducer: row r (block J=r>>7) reads slots 0..15 and 16..16+J-1
// Both are bitwise-equivalent to R11's full-init + full-scan.
// ============================================================================

#define N_TOT   8192
#define B_HALF  4096
#define TILE    128
#define THREADS 256
#define NCTA    296
#define NTILES  2080
#define SLOTS   80

#define C_L2E   14.4269504088896340736f   // (1/T)*log2(e)
#define LN2     0.69314718055994530942

#define LDB       272                      // bf16 tile row stride bytes
#define TILE_BYTES (TILE * LDB)            // 34816
#define SM_A      0
#define SM_B0     TILE_BYTES
#define SM_B1     (2 * TILE_BYTES)
#define SM_RED    (3 * TILE_BYTES)         // 6 KB reduce buffer
#define SMEM_BYTES (3 * TILE_BYTES + 6144) // 110592 -> 2 CTAs/SM

__device__ __nv_bfloat162 Zbf[N_TOT * 64];
__device__ float    g_pm[SLOTS * N_TOT];
__device__ float    g_ps[SLOTS * N_TOT];
__device__ float    g_pp[SLOTS * N_TOT];
__device__ double   g_acc;
__device__ unsigned g_done;

// ---------------------------------------------------------------------------
__device__ __forceinline__ uint32_t smem_u32(const void* p) {
    uint32_t a;
    asm("{ .reg .u64 t; cvta.to.shared.u64 t, %1; cvt.u32.u64 %0, t; }"
        : "=r"(a) : "l"(p));
    return a;
}
__device__ __forceinline__ float ex2f(float x) {
    float y; asm("ex2.approx.ftz.f32 %0, %1;" : "=f"(y) : "f"(x)); return y;
}
__device__ __forceinline__ void cp16(uint32_t dst, const void* src) {
    asm volatile("cp.async.cg.shared.global [%0], [%1], 16;" :: "r"(dst), "l"(src));
}
#define CP_COMMIT() asm volatile("cp.async.commit_group;" ::: "memory")
template <int N>
__device__ __forceinline__ void cp_wait() {
    asm volatile("cp.async.wait_group %0;" :: "n"(N) : "memory");
}
__device__ __forceinline__ void ldsm4(uint32_t& r0, uint32_t& r1,
                                      uint32_t& r2, uint32_t& r3, uint32_t a) {
    asm volatile("ldmatrix.sync.aligned.m8n8.x4.shared.b16 {%0,%1,%2,%3}, [%4];"
                 : "=r"(r0), "=r"(r1), "=r"(r2), "=r"(r3) : "r"(a));
}
__device__ __forceinline__ void ldsm2(uint32_t& r0, uint32_t& r1, uint32_t a) {
    asm volatile("ldmatrix.sync.aligned.m8n8.x2.shared.b16 {%0,%1}, [%2];"
                 : "=r"(r0), "=r"(r1) : "r"(a));
}
__device__ __forceinline__ void mma16(float& d0, float& d1, float& d2, float& d3,
                                      uint32_t a0, uint32_t a1, uint32_t a2, uint32_t a3,
                                      uint32_t b0, uint32_t b1) {
    asm volatile(
        "mma.sync.aligned.m16n8k16.row.col.f32.bf16.bf16.f32 "
        "{%0,%1,%2,%3}, {%4,%5,%6,%7}, {%8,%9}, {%0,%1,%2,%3};"
        : "+f"(d0), "+f"(d1), "+f"(d2), "+f"(d3)
        : "r"(a0), "r"(a1), "r"(a2), "r"(a3), "r"(b0), "r"(b1));
}
__device__ __forceinline__ void lse_merge(float& m1, float& s1, float m2, float s2) {
    float mn = fmaxf(m1, m2), ml = fminf(m1, m2);
    float shi = (m1 >= m2) ? s1 : s2;
    float slo = (m1 >= m2) ? s2 : s1;
    s1 = shi + slo * ex2f(ml - mn);
    m1 = mn;
}
__device__ __forceinline__ void load_tile(uint32_t sdst, int gRow0, int tid) {
    const char* src = (const char*)Zbf + (size_t)gRow0 * 256;
    #pragma unroll
    for (int it = 0; it < 8; it++) {
        int c = tid + it * THREADS;
        int row = c >> 4, q = c & 15;
        cp16(sdst + row * LDB + q * 16, src + row * 256 + q * 16);
    }
}

// ---------------------------------------------------------------------------
// slim prep: RN-convert zi||zj -> Zbf (4 bf16x2/thread), init ONLY the 16
// row-strip slots (exactly 131072 entries = one per thread), reset flags.
__global__ void infonce_prep(const float* __restrict__ zi,
                             const float* __restrict__ zj)
{
    const int i = blockIdx.x * 256 + threadIdx.x;   // 512 blocks -> 131072 thr
    #pragma unroll
    for (int r = 0; r < 4; r++) {
        const int idx = r * 131072 + i;             // bf16x2 index, < 524288
        const float2 v = (r < 2)
            ? *(const float2*)(zi + (size_t)idx * 2)
            : *(const float2*)(zj + (size_t)idx * 2 - 524288);
        Zbf[idx] = __floats2bfloat162_rn(v.x, v.y);
    }
    g_pm[i] = -1e30f; g_ps[i] = 0.0f; g_pp[i] = 0.0f;   // slots 0..15
    if (i == 0) { g_acc = 0.0; g_done = 0u; }
}

// ---------------------------------------------------------------------------
__global__ __launch_bounds__(THREADS, 2)
void infonce_mma_kernel()
{
    extern __shared__ char smem[];
    const uint32_t sb = smem_u32(smem);
    const int tid = threadIdx.x, lane = tid & 31, wid = tid >> 5;
    const int g = lane >> 2, tg = lane & 3;
    const int warpRow = wid >> 2, warpCol = wid & 3;
    const int R0 = warpRow * 64, C0w = warpCol * 32;

    const int t0 = (int)(((long long)blockIdx.x * NTILES) / NCTA);
    const int t1 = (int)(((long long)(blockIdx.x + 1) * NTILES) / NCTA);
    const int slot = blockIdx.x & 15;

    int I = 0, base = 0;
    while (base + (64 - I) <= t0) { base += 64 - I; I++; }
    int J = I + (t0 - base);

    float* redm = (float*)(smem + SM_RED);
    float* reds = redm + 512;
    float* redp = redm + 1024;

    // ldmatrix per-lane addresses
    uint32_t aAddr[4], bOff[4];
    #pragma unroll
    for (int i = 0; i < 4; i++)
        aAddr[i] = sb + SM_A + (R0 + i * 16 + (lane & 15)) * LDB + (lane >> 4) * 16;
    #pragma unroll
    for (int j = 0; j < 4; j++)
        bOff[j] = (C0w + j * 8 + (lane & 7)) * LDB + ((lane >> 3) & 1) * 16;

    load_tile(sb + SM_A,  I * TILE, tid);
    load_tile(sb + SM_B0, J * TILE, tid);
    CP_COMMIT();

    float m[8], s[8], pv[8];
    #pragma unroll
    for (int r = 0; r < 8; r++) { m[r] = -1e30f; s[r] = 0.0f; pv[r] = 0.0f; }

    for (int t = t0; t < t1; t++) {
        const int lt = t - t0;
        int In = I, Jn = J + 1;
        if (Jn == 64) { In = I + 1; Jn = In; }

        cp_wait<0>();
        __syncthreads();
        if (t + 1 < t1) {               // prefetch next B a full tile ahead
            load_tile((lt & 1) ? sb + SM_B0 : sb + SM_B1, Jn * TILE, tid);
            CP_COMMIT();
        }

        const uint32_t bBase = sb + ((lt & 1) ? SM_B1 : SM_B0);
        const int tileC0 = J * TILE + C0w;
        const int rowBase = I * TILE + R0;

        float acc[4][4][4];
        #pragma unroll
        for (int i = 0; i < 4; i++)
            #pragma unroll
            for (int j = 0; j < 4; j++)
                #pragma unroll
                for (int c = 0; c < 4; c++) acc[i][j][c] = 0.0f;

        #pragma unroll 4
        for (int ks = 0; ks < 8; ks++) {
            const uint32_t ko = ks * 32;        // 16 bf16 per k-step
            uint32_t A0[4], A1[4], A2[4], A3[4];
            #pragma unroll
            for (int i = 0; i < 4; i++)
                ldsm4(A0[i], A1[i], A2[i], A3[i], aAddr[i] + ko);
            uint32_t B0r[4], B1r[4];
            #pragma unroll
            for (int j = 0; j < 4; j++)
                ldsm2(B0r[j], B1r[j], bBase + bOff[j] + ko);
            #pragma unroll
            for (int i = 0; i < 4; i++)
                #pragma unroll
                for (int j = 0; j < 4; j++)
                    mma16(acc[i][j][0], acc[i][j][1], acc[i][j][2], acc[i][j][3],
                          A0[i], A1[i], A2[i], A3[i], B0r[j], B1r[j]);
        }

        // ---- row-wise online LSE (rows of block I)
        #pragma unroll
        for (int i = 0; i < 4; i++) {
            #pragma unroll
            for (int h = 0; h < 2; h++) {
                const int ri = i * 2 + h;
                const int rowg = rowBase + i * 16 + h * 8 + g;
                const int prow = rowg ^ B_HALF;
                float f[8], rmax = -1e30f;
                #pragma unroll
                for (int j = 0; j < 4; j++) {
                    #pragma unroll
                    for (int qq = 0; qq < 2; qq++) {
                        const int colg = tileC0 + j * 8 + tg * 2 + qq;
                        float v = acc[i][j][h * 2 + qq] * C_L2E;
                        if (colg == rowg) v = -1e30f;
                        if (colg == prow) pv[ri] = v;
                        f[j * 2 + qq] = v;
                        rmax = fmaxf(rmax, v);
                    }
                }
                if (rmax > m[ri] - 27.0f) {
                    const float mn = fmaxf(m[ri], rmax);
                    float acc_s = s[ri] * ex2f(m[ri] - mn);
                    #pragma unroll
                    for (int x = 0; x < 8; x++) acc_s += ex2f(f[x] - mn);
                    m[ri] = mn; s[ri] = acc_s;
                }
            }
        }

        // ---- column-wise LSE partials (rows of block J)
        if (J > I) {
            float tm[8], ts[8], tp[8];
            #pragma unroll
            for (int j = 0; j < 4; j++) {
                #pragma unroll
                for (int qq = 0; qq < 2; qq++) {
                    const int ci = j * 2 + qq;
                    const int colg = tileC0 + j * 8 + tg * 2 + qq;
                    const int target = colg ^ B_HALF;
                    float mx = -1e30f;
                    #pragma unroll
                    for (int i = 0; i < 4; i++)
                        mx = fmaxf(mx, fmaxf(acc[i][j][qq], acc[i][j][2 + qq]));
                    mx *= C_L2E;
                    float ssum = 0.0f, pvv = 0.0f;
                    #pragma unroll
                    for (int i = 0; i < 4; i++) {
                        #pragma unroll
                        for (int h = 0; h < 2; h++) {
                            const float v = acc[i][j][h * 2 + qq] * C_L2E;
                            const int rowg = rowBase + i * 16 + h * 8 + g;
                            if (rowg == target) pvv = v;
                            ssum += ex2f(v - mx);
                        }
                    }
                    tm[ci] = mx; ts[ci] = ssum; tp[ci] = pvv;
                }
            }
            #pragma unroll
            for (int off = 4; off <= 16; off <<= 1) {
                #pragma unroll
                for (int ci = 0; ci < 8; ci++) {
                    float mo = __shfl_xor_sync(0xffffffffu, tm[ci], off);
                    float so = __shfl_xor_sync(0xffffffffu, ts[ci], off);
                    float po = __shfl_xor_sync(0xffffffffu, tp[ci], off);
                    lse_merge(tm[ci], ts[ci], mo, so);
                    tp[ci] += po;
                }
            }
            __syncthreads();
            if (warpRow == 1 && g == 0) {
                #pragma unroll
                for (int ci = 0; ci < 8; ci++) {
                    const int cl = C0w + (ci >> 1) * 8 + tg * 2 + (ci & 1);
                    redm[cl * 3 + 0] = tm[ci];
                    redm[cl * 3 + 1] = ts[ci];
                    redm[cl * 3 + 2] = tp[ci];
                }
            }
            __syncthreads();
            if (warpRow == 0 && g == 0) {
                const int cslot = 16 + I;
                #pragma unroll
                for (int ci = 0; ci < 8; ci++) {
                    const int cl = C0w + (ci >> 1) * 8 + tg * 2 + (ci & 1);
                    lse_merge(tm[ci], ts[ci], redm[cl * 3 + 0], redm[cl * 3 + 1]);
                    tp[ci] += redm[cl * 3 + 2];
                    const int gr = J * TILE + cl;
                    g_pm[cslot * N_TOT + gr] = tm[ci];
                    g_ps[cslot * N_TOT + gr] = ts[ci];
                    g_pp[cslot * N_TOT + gr] = tp[ci];
                }
            }
        }

        // ---- segment flush (row transition or final tile)
        const bool lastT = (t + 1 == t1);
        if (lastT || In != I) {
            #pragma unroll
            for (int ri = 0; ri < 8; ri++) {
                #pragma unroll
                for (int off = 1; off < 4; off <<= 1) {
                    float mo = __shfl_xor_sync(0xffffffffu, m[ri],  off);
                    float so = __shfl_xor_sync(0xffffffffu, s[ri],  off);
                    float po = __shfl_xor_sync(0xffffffffu, pv[ri], off);
                    lse_merge(m[ri], s[ri], mo, so);
                    pv[ri] += po;
                }
            }
            __syncthreads();
            if (tg == 0) {
                #pragma unroll
                for (int ri = 0; ri < 8; ri++) {
                    const int rl = R0 + (ri >> 1) * 16 + (ri & 1) * 8 + g;
                    redm[rl * 4 + warpCol] = m[ri];
                    reds[rl * 4 + warpCol] = s[ri];
                    redp[rl * 4 + warpCol] = pv[ri];
                }
            }
            __syncthreads();
            if (tid < TILE) {
                float M = redm[tid * 4 + 0], S = reds[tid * 4 + 0], P = redp[tid * 4 + 0];
                #pragma unroll
                for (int wq = 1; wq < 4; wq++) {
                    lse_merge(M, S, redm[tid * 4 + wq], reds[tid * 4 + wq]);
                    P += redp[tid * 4 + wq];
                }
                const int idx = slot * N_TOT + I * TILE + tid;
                g_pm[idx] = M; g_ps[idx] = S; g_pp[idx] = P;
            }
            if (!lastT) {
                __syncthreads();
                #pragma unroll
                for (int r = 0; r < 8; r++) { m[r] = -1e30f; s[r] = 0.0f; pv[r] = 0.0f; }
                load_tile(sb + SM_A, In * TILE, tid);
                CP_COMMIT();
            }
        }

        I = In; J = Jn;
    }
}

// ---------------------------------------------------------------------------
// adaptive reducer: row r (block J = r>>7) merges row slots 0..15 and col
// slots 16..16+J-1 (exactly the written ones); identical result to full scan.
__global__ void infonce_reduce(float* out)
{
    const int r = blockIdx.x * 256 + threadIdx.x;   // 32 x 256 = 8192
    const int J = r >> 7;
    float M = -1e30f, S = 0.0f, P = 0.0f;
    #pragma unroll 4
    for (int k = 0; k < 16; k++) {
        lse_merge(M, S, g_pm[k * N_TOT + r], g_ps[k * N_TOT + r]);
        P += g_pp[k * N_TOT + r];
    }
    const int kend = 16 + J;
    for (int k = 16; k < kend; k++) {
        lse_merge(M, S, g_pm[k * N_TOT + r], g_ps[k * N_TOT + r]);
        P += g_pp[k * N_TOT + r];
    }
    S += ex2f(P - M);                  // positive's logits[:,0] copy
    float val = M + log2f(S) - P;

    __shared__ double redd[256];
    redd[threadIdx.x] = (double)val;
    __syncthreads();
    #pragma unroll
    for (int off = 128; off > 0; off >>= 1) {
        if (threadIdx.x < off) redd[threadIdx.x] += redd[threadIdx.x + off];
        __syncthreads();
    }
    if (threadIdx.x == 0) {
        atomicAdd(&g_acc, redd[0]);
        __threadfence();
        unsigned done = atomicAdd(&g_done, 1u);
        if (done == 31u) {
            __threadfence();
            out[0] = (float)(g_acc * LN2 / (double)N_TOT);
        }
    }
}

// ---------------------------------------------------------------------------
extern "C" void kernel_launch(void* const* d_in, const int* in_sizes, int n_in,
                              void* d_out, int out_size)
{
    const float* zi = (const float*)d_in[0];
    const float* zj = (const float*)d_in[1];
    float* out = (float*)d_out;

    static bool attr_set = false;
    if (!attr_set) {
        cudaFuncSetAttribute(infonce_mma_kernel,
                             cudaFuncAttributeMaxDynamicSharedMemorySize, SMEM_BYTES);
        attr_set = true;
    }

    infonce_prep<<<512, 256>>>(zi, zj);
    infonce_mma_kernel<<<NCTA, THREADS, SMEM_BYTES>>>();
    infonce_reduce<<<32, 256>>>(out);
}

// round 17
// speedup vs baseline: 1.1080x; 1.1080x over previous
#include <cuda_runtime.h>
#include <cuda_bf16.h>
#include <cstdint>
#include <math.h>

// ============================================================================
// InfoNCE / NT-Xent via mma.sync bf16 m16n8k16 + ldmatrix, sim = sim^T
// (upper-triangular 128x128 tiles, 2080). Persistent 296 CTAs (2/SM).
// Main kernel BYTE-IDENTICAL to the proven 62.0us R11 winner.
// New: zero-init scheme — prep only converts (no slot init); the reducer
// computes, per row-block I, the exact contiguous bid window covering it
// (bid(t) = floor(((t+1)*296-1)/2080)) and merges only those row slots
// (b & 15), plus adaptive col slots 16..16+I-1 (proven in R13).
// ============================================================================

#define N_TOT   8192
#define B_HALF  4096
#define TILE    128
#define THREADS 256
#define NCTA    296
#define NTILES  2080
#define SLOTS   80

#define C_L2E   14.4269504088896340736f   // (1/T)*log2(e)
#define LN2     0.69314718055994530942

#define LDB       272                      // bf16 tile row stride bytes
#define TILE_BYTES (TILE * LDB)            // 34816
#define SM_A      0
#define SM_B0     TILE_BYTES
#define SM_B1     (2 * TILE_BYTES)
#define SM_RED    (3 * TILE_BYTES)         // 6 KB reduce buffer
#define SMEM_BYTES (3 * TILE_BYTES + 6144) // 110592 -> 2 CTAs/SM

__device__ __nv_bfloat162 Zbf[N_TOT * 64];
__device__ float    g_pm[SLOTS * N_TOT];
__device__ float    g_ps[SLOTS * N_TOT];
__device__ float    g_pp[SLOTS * N_TOT];
__device__ double   g_acc;
__device__ unsigned g_done;

// ---------------------------------------------------------------------------
__device__ __forceinline__ uint32_t smem_u32(const void* p) {
    uint32_t a;
    asm("{ .reg .u64 t; cvta.to.shared.u64 t, %1; cvt.u32.u64 %0, t; }"
        : "=r"(a) : "l"(p));
    return a;
}
__device__ __forceinline__ float ex2f(float x) {
    float y; asm("ex2.approx.ftz.f32 %0, %1;" : "=f"(y) : "f"(x)); return y;
}
__device__ __forceinline__ void cp16(uint32_t dst, const void* src) {
    asm volatile("cp.async.cg.shared.global [%0], [%1], 16;" :: "r"(dst), "l"(src));
}
#define CP_COMMIT() asm volatile("cp.async.commit_group;" ::: "memory")
template <int N>
__device__ __forceinline__ void cp_wait() {
    asm volatile("cp.async.wait_group %0;" :: "n"(N) : "memory");
}
__device__ __forceinline__ void ldsm4(uint32_t& r0, uint32_t& r1,
                                      uint32_t& r2, uint32_t& r3, uint32_t a) {
    asm volatile("ldmatrix.sync.aligned.m8n8.x4.shared.b16 {%0,%1,%2,%3}, [%4];"
                 : "=r"(r0), "=r"(r1), "=r"(r2), "=r"(r3) : "r"(a));
}
__device__ __forceinline__ void ldsm2(uint32_t& r0, uint32_t& r1, uint32_t a) {
    asm volatile("ldmatrix.sync.aligned.m8n8.x2.shared.b16 {%0,%1}, [%2];"
                 : "=r"(r0), "=r"(r1) : "r"(a));
}
__device__ __forceinline__ void mma16(float& d0, float& d1, float& d2, float& d3,
                                      uint32_t a0, uint32_t a1, uint32_t a2, uint32_t a3,
                                      uint32_t b0, uint32_t b1) {
    asm volatile(
        "mma.sync.aligned.m16n8k16.row.col.f32.bf16.bf16.f32 "
        "{%0,%1,%2,%3}, {%4,%5,%6,%7}, {%8,%9}, {%0,%1,%2,%3};"
        : "+f"(d0), "+f"(d1), "+f"(d2), "+f"(d3)
        : "r"(a0), "r"(a1), "r"(a2), "r"(a3), "r"(b0), "r"(b1));
}
__device__ __forceinline__ void lse_merge(float& m1, float& s1, float m2, float s2) {
    float mn = fmaxf(m1, m2), ml = fminf(m1, m2);
    float shi = (m1 >= m2) ? s1 : s2;
    float slo = (m1 >= m2) ? s2 : s1;
    s1 = shi + slo * ex2f(ml - mn);
    m1 = mn;
}
__device__ __forceinline__ void load_tile(uint32_t sdst, int gRow0, int tid) {
    const char* src = (const char*)Zbf + (size_t)gRow0 * 256;
    #pragma unroll
    for (int it = 0; it < 8; it++) {
        int c = tid + it * THREADS;
        int row = c >> 4, q = c & 15;
        cp16(sdst + row * LDB + q * 16, src + row * 256 + q * 16);
    }
}

// ---------------------------------------------------------------------------
// prep: conversion only (no slot init needed — reducer reads only written
// slots). Layout identical to R11's conversion.
__global__ void infonce_prep(const float* __restrict__ zi,
                             const float* __restrict__ zj)
{
    const int i = blockIdx.x * 256 + threadIdx.x;   // 2048*256 = 524288
    const int e = i * 2;
    const float2 v = (e < B_HALF * 128)
        ? *(const float2*)(zi + e)
        : *(const float2*)(zj + (e - B_HALF * 128));
    Zbf[i] = __floats2bfloat162_rn(v.x, v.y);
    if (i == 0) { g_acc = 0.0; g_done = 0u; }
}

// ---------------------------------------------------------------------------
// main kernel — byte-identical to R11 (62.0us winner)
__global__ __launch_bounds__(THREADS, 2)
void infonce_mma_kernel()
{
    extern __shared__ char smem[];
    const uint32_t sb = smem_u32(smem);
    const int tid = threadIdx.x, lane = tid & 31, wid = tid >> 5;
    const int g = lane >> 2, tg = lane & 3;
    const int warpRow = wid >> 2, warpCol = wid & 3;
    const int R0 = warpRow * 64, C0w = warpCol * 32;

    const int t0 = (int)(((long long)blockIdx.x * NTILES) / NCTA);
    const int t1 = (int)(((long long)(blockIdx.x + 1) * NTILES) / NCTA);
    const int slot = blockIdx.x & 15;

    int I = 0, base = 0;
    while (base + (64 - I) <= t0) { base += 64 - I; I++; }
    int J = I + (t0 - base);

    float* redm = (float*)(smem + SM_RED);
    float* reds = redm + 512;
    float* redp = redm + 1024;

    uint32_t aAddr[4], bOff[4];
    #pragma unroll
    for (int i = 0; i < 4; i++)
        aAddr[i] = sb + SM_A + (R0 + i * 16 + (lane & 15)) * LDB + (lane >> 4) * 16;
    #pragma unroll
    for (int j = 0; j < 4; j++)
        bOff[j] = (C0w + j * 8 + (lane & 7)) * LDB + ((lane >> 3) & 1) * 16;

    load_tile(sb + SM_A,  I * TILE, tid);
    load_tile(sb + SM_B0, J * TILE, tid);
    CP_COMMIT();

    float m[8], s[8], pv[8];
    #pragma unroll
    for (int r = 0; r < 8; r++) { m[r] = -1e30f; s[r] = 0.0f; pv[r] = 0.0f; }

    for (int t = t0; t < t1; t++) {
        const int lt = t - t0;
        int In = I, Jn = J + 1;
        if (Jn == 64) { In = I + 1; Jn = In; }

        cp_wait<0>();
        __syncthreads();
        if (t + 1 < t1) {               // prefetch next B a full tile ahead
            load_tile((lt & 1) ? sb + SM_B0 : sb + SM_B1, Jn * TILE, tid);
            CP_COMMIT();
        }

        const uint32_t bBase = sb + ((lt & 1) ? SM_B1 : SM_B0);
        const int tileC0 = J * TILE + C0w;
        const int rowBase = I * TILE + R0;

        float acc[4][4][4];
        #pragma unroll
        for (int i = 0; i < 4; i++)
            #pragma unroll
            for (int j = 0; j < 4; j++)
                #pragma unroll
                for (int c = 0; c < 4; c++) acc[i][j][c] = 0.0f;

        #pragma unroll 4
        for (int ks = 0; ks < 8; ks++) {
            const uint32_t ko = ks * 32;        // 16 bf16 per k-step
            uint32_t A0[4], A1[4], A2[4], A3[4];
            #pragma unroll
            for (int i = 0; i < 4; i++)
                ldsm4(A0[i], A1[i], A2[i], A3[i], aAddr[i] + ko);
            uint32_t B0r[4], B1r[4];
            #pragma unroll
            for (int j = 0; j < 4; j++)
                ldsm2(B0r[j], B1r[j], bBase + bOff[j] + ko);
            #pragma unroll
            for (int i = 0; i < 4; i++)
                #pragma unroll
                for (int j = 0; j < 4; j++)
                    mma16(acc[i][j][0], acc[i][j][1], acc[i][j][2], acc[i][j][3],
                          A0[i], A1[i], A2[i], A3[i], B0r[j], B1r[j]);
        }

        // ---- row-wise online LSE (rows of block I)
        #pragma unroll
        for (int i = 0; i < 4; i++) {
            #pragma unroll
            for (int h = 0; h < 2; h++) {
                const int ri = i * 2 + h;
                const int rowg = rowBase + i * 16 + h * 8 + g;
                const int prow = rowg ^ B_HALF;
                float f[8], rmax = -1e30f;
                #pragma unroll
                for (int j = 0; j < 4; j++) {
                    #pragma unroll
                    for (int qq = 0; qq < 2; qq++) {
                        const int colg = tileC0 + j * 8 + tg * 2 + qq;
                        float v = acc[i][j][h * 2 + qq] * C_L2E;
                        if (colg == rowg) v = -1e30f;
                        if (colg == prow) pv[ri] = v;
                        f[j * 2 + qq] = v;
                        rmax = fmaxf(rmax, v);
                    }
                }
                if (rmax > m[ri] - 27.0f) {
                    const float mn = fmaxf(m[ri], rmax);
                    float acc_s = s[ri] * ex2f(m[ri] - mn);
                    #pragma unroll
                    for (int x = 0; x < 8; x++) acc_s += ex2f(f[x] - mn);
                    m[ri] = mn; s[ri] = acc_s;
                }
            }
        }

        // ---- column-wise LSE partials (rows of block J)
        if (J > I) {
            float tm[8], ts[8], tp[8];
            #pragma unroll
            for (int j = 0; j < 4; j++) {
                #pragma unroll
                for (int qq = 0; qq < 2; qq++) {
                    const int ci = j * 2 + qq;
                    const int colg = tileC0 + j * 8 + tg * 2 + qq;
                    const int target = colg ^ B_HALF;
                    float mx = -1e30f;
                    #pragma unroll
                    for (int i = 0; i < 4; i++)
                        mx = fmaxf(mx, fmaxf(acc[i][j][qq], acc[i][j][2 + qq]));
                    mx *= C_L2E;
                    float ssum = 0.0f, pvv = 0.0f;
                    #pragma unroll
                    for (int i = 0; i < 4; i++) {
                        #pragma unroll
                        for (int h = 0; h < 2; h++) {
                            const float v = acc[i][j][h * 2 + qq] * C_L2E;
                            const int rowg = rowBase + i * 16 + h * 8 + g;
                            if (rowg == target) pvv = v;
                            ssum += ex2f(v - mx);
                        }
                    }
                    tm[ci] = mx; ts[ci] = ssum; tp[ci] = pvv;
                }
            }
            #pragma unroll
            for (int off = 4; off <= 16; off <<= 1) {
                #pragma unroll
                for (int ci = 0; ci < 8; ci++) {
                    float mo = __shfl_xor_sync(0xffffffffu, tm[ci], off);
                    float so = __shfl_xor_sync(0xffffffffu, ts[ci], off);
                    float po = __shfl_xor_sync(0xffffffffu, tp[ci], off);
                    lse_merge(tm[ci], ts[ci], mo, so);
                    tp[ci] += po;
                }
            }
            __syncthreads();
            if (warpRow == 1 && g == 0) {
                #pragma unroll
                for (int ci = 0; ci < 8; ci++) {
                    const int cl = C0w + (ci >> 1) * 8 + tg * 2 + (ci & 1);
                    redm[cl * 3 + 0] = tm[ci];
                    redm[cl * 3 + 1] = ts[ci];
                    redm[cl * 3 + 2] = tp[ci];
                }
            }
            __syncthreads();
            if (warpRow == 0 && g == 0) {
                const int cslot = 16 + I;
                #pragma unroll
                for (int ci = 0; ci < 8; ci++) {
                    const int cl = C0w + (ci >> 1) * 8 + tg * 2 + (ci & 1);
                    lse_merge(tm[ci], ts[ci], redm[cl * 3 + 0], redm[cl * 3 + 1]);
                    tp[ci] += redm[cl * 3 + 2];
                    const int gr = J * TILE + cl;
                    g_pm[cslot * N_TOT + gr] = tm[ci];
                    g_ps[cslot * N_TOT + gr] = ts[ci];
                    g_pp[cslot * N_TOT + gr] = tp[ci];
                }
            }
        }

        // ---- segment flush (row transition or final tile)
        const bool lastT = (t + 1 == t1);
        if (lastT || In != I) {
            #pragma unroll
            for (int ri = 0; ri < 8; ri++) {
                #pragma unroll
                for (int off = 1; off < 4; off <<= 1) {
                    float mo = __shfl_xor_sync(0xffffffffu, m[ri],  off);
                    float so = __shfl_xor_sync(0xffffffffu, s[ri],  off);
                    float po = __shfl_xor_sync(0xffffffffu, pv[ri], off);
                    lse_merge(m[ri], s[ri], mo, so);
                    pv[ri] += po;
                }
            }
            __syncthreads();
            if (tg == 0) {
                #pragma unroll
                for (int ri = 0; ri < 8; ri++) {
                    const int rl = R0 + (ri >> 1) * 16 + (ri & 1) * 8 + g;
                    redm[rl * 4 + warpCol] = m[ri];
                    reds[rl * 4 + warpCol] = s[ri];
                    redp[rl * 4 + warpCol] = pv[ri];
                }
            }
            __syncthreads();
            if (tid < TILE) {
                float M = redm[tid * 4 + 0], S = reds[tid * 4 + 0], P = redp[tid * 4 + 0];
                #pragma unroll
                for (int wq = 1; wq < 4; wq++) {
                    lse_merge(M, S, redm[tid * 4 + wq], reds[tid * 4 + wq]);
                    P += redp[tid * 4 + wq];
                }
                const int idx = slot * N_TOT + I * TILE + tid;
                g_pm[idx] = M; g_ps[idx] = S; g_pp[idx] = P;
            }
            if (!lastT) {
                __syncthreads();
                #pragma unroll
                for (int r = 0; r < 8; r++) { m[r] = -1e30f; s[r] = 0.0f; pv[r] = 0.0f; }
                load_tile(sb + SM_A, In * TILE, tid);
                CP_COMMIT();
            }
        }

        I = In; J = Jn;
    }
}

// ---------------------------------------------------------------------------
// windowed reducer: for row r (block I = r>>7), merge exactly the row slots
// written by the bid window covering block I, then col slots 16..16+I-1.
// 64 blocks x 128 threads; counter-gated final write.
__global__ void infonce_reduce(float* out)
{
    const int r = blockIdx.x * 128 + threadIdx.x;   // 64 x 128 = 8192
    const int Ib = r >> 7;

    // tile range of row-block Ib: [bI, eI)
    const int bI = 64 * Ib - (Ib * (Ib - 1)) / 2;
    const int eI = bI + (64 - Ib);
    // bid(t) = floor(((t+1)*NCTA - 1) / NTILES)
    const int bidLo = (int)(((long long)(bI + 1) * NCTA - 1) / NTILES);
    const int bidHi = (int)(((long long)eI * NCTA - 1) / NTILES);

    float M = -1e30f, S = 0.0f, P = 0.0f;
    bool first = true;
    for (int b = bidLo; b <= bidHi; b++) {
        const int k = b & 15;
        if (first) { M = g_pm[k * N_TOT + r]; S = g_ps[k * N_TOT + r];
                     P = g_pp[k * N_TOT + r]; first = false; }
        else {
            lse_merge(M, S, g_pm[k * N_TOT + r], g_ps[k * N_TOT + r]);
            P += g_pp[k * N_TOT + r];
        }
    }
    const int kend = 16 + Ib;       // col slots 16..16+Ib-1
    for (int k = 16; k < kend; k++) {
        lse_merge(M, S, g_pm[k * N_TOT + r], g_ps[k * N_TOT + r]);
        P += g_pp[k * N_TOT + r];
    }
    S += ex2f(P - M);               // positive's logits[:,0] copy
    float val = M + log2f(S) - P;

    __shared__ double redd[128];
    redd[threadIdx.x] = (double)val;
    __syncthreads();
    #pragma unroll
    for (int off = 64; off > 0; off >>= 1) {
        if (threadIdx.x < off) redd[threadIdx.x] += redd[threadIdx.x + off];
        __syncthreads();
    }
    if (threadIdx.x == 0) {
        atomicAdd(&g_acc, redd[0]);
        __threadfence();
        unsigned done = atomicAdd(&g_done, 1u);
        if (done == 63u) {
            __threadfence();
            out[0] = (float)(g_acc * LN2 / (double)N_TOT);
        }
    }
}

// ---------------------------------------------------------------------------
extern "C" void kernel_launch(void* const* d_in, const int* in_sizes, int n_in,
                              void* d_out, int out_size)
{
    const float* zi = (const float*)d_in[0];
    const float* zj = (const float*)d_in[1];
    float* out = (float*)d_out;

    static bool attr_set = false;
    if (!attr_set) {
        cudaFuncSetAttribute(infonce_mma_kernel,
                             cudaFuncAttributeMaxDynamicSharedMemorySize, SMEM_BYTES);
        attr_set = true;
    }

    infonce_prep<<<2048, 256>>>(zi, zj);
    infonce_mma_kernel<<<NCTA, THREADS, SMEM_BYTES>>>();
    infonce_reduce<<<64, 128>>>(out);
}